// round 7
// baseline (speedup 1.0000x reference)
#include <cuda_runtime.h>
#include <math.h>

// KarplusStrongResonator: (1 + q) Y = X, q = a1 z^-d1 + a2 z^-d2,
// d1 = 61 + argmax(delay_param + gumbel), d2 = 61 + ((argmax+1) % 360).
// Triple recurrence-doubling: (1-q)(1+q^2)(1+q^4) both sides ->
// (1 - q^8) Y = X3, three fully parallel FIR passes then a 9-tap
// recurrence with min lag 8*min(d1,d2) >= 488 -> <=17 chunk barriers.

#define T_LEN 8192
#define B_ROWS 128
#define NDELAY 360
#define NT 512
#define NWARP (NT / 32)

__global__ __launch_bounds__(NT, 1)
void ks_resonator_kernel(const float* __restrict__ x,
                         const float* __restrict__ gumbel,
                         const float* __restrict__ dparam,
                         const float* __restrict__ fgain,
                         const float* __restrict__ refl,
                         float* __restrict__ out)
{
    extern __shared__ float smem[];
    float* A = smem;            // [T_LEN]
    float* B = smem + T_LEN;    // [T_LEN]

    __shared__ float red_v[NWARP];
    __shared__ int   red_i[NWARP];
    __shared__ float s_a1, s_a2;
    __shared__ int   s_d1, s_d2;

    const int tid  = threadIdx.x;
    const int lane = tid & 31;
    const int wid  = tid >> 5;
    const int row  = blockIdx.x;

    // ---- async prefetch of x row into A (non-blocking; overlaps argmax) ----
    {
        const char* gsrc = (const char*)(x + (size_t)row * T_LEN);
        #pragma unroll
        for (int i = tid; i < T_LEN / 4; i += NT) {
            unsigned sdst = (unsigned)__cvta_generic_to_shared(A + 4 * i);
            asm volatile("cp.async.cg.shared.global [%0], [%1], 16;\n"
                         :: "r"(sdst), "l"(gsrc + 16 * (size_t)i));
        }
        asm volatile("cp.async.commit_group;\n");
    }

    // ---- argmax(delay_param + gumbel) via shuffles (overlapped with cp.async) ----
    {
        float v = -INFINITY;
        int   idx = 0;
        if (tid < NDELAY) { v = dparam[tid] + gumbel[tid]; idx = tid; }
        #pragma unroll
        for (int off = 16; off > 0; off >>= 1) {
            float v2 = __shfl_down_sync(0xffffffffu, v, off);
            int   i2 = __shfl_down_sync(0xffffffffu, idx, off);
            if (v2 > v || (v2 == v && i2 < idx)) { v = v2; idx = i2; }
        }
        if (lane == 0) { red_v[wid] = v; red_i[wid] = idx; }
        __syncthreads();
        if (wid == 0) {
            float vv = (lane < NWARP) ? red_v[lane] : -INFINITY;
            int   ii = (lane < NWARP) ? red_i[lane] : 0;
            #pragma unroll
            for (int off = 8; off > 0; off >>= 1) {
                float v2 = __shfl_down_sync(0xffffffffu, vv, off);
                int   i2 = __shfl_down_sync(0xffffffffu, ii, off);
                if (v2 > vv || (v2 == vv && i2 < ii)) { vv = v2; ii = i2; }
            }
            if (lane == 0) {
                int j = ii;
                float k1 = tanhf(tanhf(refl[0]));  // resonant_activation(tanh(rc), tau=0)
                float k2 = tanhf(tanhf(refl[1]));
                float a1 = k1 * (1.0f - k2);
                float a2 = fminf(fmaxf(k2, -0.999f), 0.999f);
                float a1b = 0.999f - fabsf(a2);
                a1 = fminf(fmaxf(a1, -a1b), a1b);
                float g = powf(1.0f / (1.0f + expf(-fgain[0])), 0.45f);
                s_a1 = a1 * g;
                s_a2 = a2 * g;
                s_d1 = 61 + j;
                s_d2 = 61 + ((j + 1) % NDELAY);
            }
        }
    }

    // ---- wait for x data + coefficients ----
    asm volatile("cp.async.wait_group 0;\n");
    __syncthreads();

    const float a1 = s_a1, a2 = s_a2;
    const int d1 = s_d1, d2 = s_d2;

    // q^2 taps
    const float c20 = a1 * a1, c21 = 2.0f * a1 * a2, c22 = a2 * a2;
    const int   l20 = 2 * d1,  l21 = d1 + d2,        l22 = 2 * d2;

    // q^4 taps
    const float c40 = c20 * c20;
    const float c41 = 4.0f * c20 * a1 * a2;
    const float c42 = 6.0f * c20 * c22;
    const float c43 = 4.0f * a1 * a2 * c22;
    const float c44 = c22 * c22;
    const int   l40 = 4 * d1, l41 = 3 * d1 + d2, l42 = 2 * (d1 + d2),
                l43 = d1 + 3 * d2, l44 = 4 * d2;

    // q^8 taps: C(8,i) a1^i a2^(8-i), lag i*d1 + (8-i)*d2
    const float p1 = a1, p2 = a2;
    const float q8[9] = {
        c44 * c44,                       // a2^8
        8.0f  * p1 * c22 * c22 * c22 * p2,  // 8 a1 a2^7
        28.0f * c20 * c22 * c22 * c22,      // 28 a1^2 a2^6
        56.0f * c20 * p1 * c22 * c22 * p2,  // 56 a1^3 a2^5
        70.0f * c40 * c44,                  // 70 a1^4 a2^4
        56.0f * c40 * p1 * c22 * p2,        // 56 a1^5 a2^3
        28.0f * c40 * c20 * c22,            // 28 a1^6 a2^2
        8.0f  * c40 * c20 * p1 * p2,        // 8 a1^7 a2
        c40 * c40                           // a1^8
    };
    int lg[9];
    #pragma unroll
    for (int i = 0; i < 9; i++) lg[i] = i * d1 + (8 - i) * d2;
    const int lmax = max(lg[0], lg[8]);
    const int Cq = 8 * min(d1, d2);     // dependency-free chunk >= 488

    // ---- pass 0: B = (1 - q) A ----
    #pragma unroll 4
    for (int t = tid; t < T_LEN; t += NT) {
        float va = (t >= d1) ? A[t - d1] : 0.0f;
        float vb = (t >= d2) ? A[t - d2] : 0.0f;
        B[t] = fmaf(-a1, va, fmaf(-a2, vb, A[t]));
    }
    __syncthreads();

    // ---- pass 1: A = (1 + q^2) B ----
    #pragma unroll 4
    for (int t = tid; t < T_LEN; t += NT) {
        float v0 = (t >= l20) ? B[t - l20] : 0.0f;
        float v1 = (t >= l21) ? B[t - l21] : 0.0f;
        float v2 = (t >= l22) ? B[t - l22] : 0.0f;
        A[t] = fmaf(c20, v0, fmaf(c21, v1, fmaf(c22, v2, B[t])));
    }
    __syncthreads();

    // ---- pass 2: B = (1 + q^4) A ----
    #pragma unroll 4
    for (int t = tid; t < T_LEN; t += NT) {
        float v0 = (t >= l40) ? A[t - l40] : 0.0f;
        float v1 = (t >= l41) ? A[t - l41] : 0.0f;
        float v2 = (t >= l42) ? A[t - l42] : 0.0f;
        float v3 = (t >= l43) ? A[t - l43] : 0.0f;
        float v4 = (t >= l44) ? A[t - l44] : 0.0f;
        float acc0 = fmaf(c40, v0, fmaf(c41, v1, A[t]));
        float acc1 = fmaf(c42, v2, fmaf(c43, v3, c44 * v4));
        B[t] = acc0 + acc1;
    }
    __syncthreads();

    // ---- recurrence: y[t] = B[t] + q^8 * y, in place on B ----
    // lags >= Cq (chunk size) so all reads land in completed chunks.
    for (int base = 0; base < T_LEN; base += Cq) {
        const int end = min(base + Cq, T_LEN);
        if (base >= lmax) {
            for (int t = base + tid; t < end; t += NT) {
                float acc0 = fmaf(q8[0], B[t - lg[0]], B[t]);
                float acc1 = fmaf(q8[1], B[t - lg[1]], q8[2] * B[t - lg[2]]);
                float acc2 = fmaf(q8[3], B[t - lg[3]], q8[4] * B[t - lg[4]]);
                float acc3 = fmaf(q8[5], B[t - lg[5]], q8[6] * B[t - lg[6]]);
                float acc4 = fmaf(q8[7], B[t - lg[7]], q8[8] * B[t - lg[8]]);
                B[t] = (acc0 + acc1) + ((acc2 + acc3) + acc4);
            }
        } else {
            for (int t = base + tid; t < end; t += NT) {
                float acc = B[t];
                #pragma unroll
                for (int i = 0; i < 9; i++)
                    acc = fmaf(q8[i], (t >= lg[i]) ? B[t - lg[i]] : 0.0f, acc);
                B[t] = acc;
            }
        }
        __syncthreads();
    }

    // ---- coalesced writeback ----
    {
        float4* o4 = reinterpret_cast<float4*>(out + (size_t)row * T_LEN);
        const float4* y4 = reinterpret_cast<const float4*>(B);
        #pragma unroll
        for (int i = tid; i < T_LEN / 4; i += NT) o4[i] = y4[i];
    }
}

extern "C" void kernel_launch(void* const* d_in, const int* in_sizes, int n_in,
                              void* d_out, int out_size)
{
    const float* excitation = (const float*)d_in[0];  // (128,1,8192)
    const float* gumbel     = (const float*)d_in[1];  // (360,)
    const float* dparam     = (const float*)d_in[2];  // (360,)
    const float* fgain      = (const float*)d_in[3];  // (1,)
    const float* refl       = (const float*)d_in[4];  // (2,)
    float* out = (float*)d_out;                       // (128,1,8192)

    const int smem_bytes = 2 * T_LEN * sizeof(float); // 64 KB dynamic
    cudaFuncSetAttribute(ks_resonator_kernel,
                         cudaFuncAttributeMaxDynamicSharedMemorySize, smem_bytes);

    ks_resonator_kernel<<<B_ROWS, NT, smem_bytes>>>(
        excitation, gumbel, dparam, fgain, refl, out);
}

// round 10
// speedup vs baseline: 1.2099x; 1.2099x over previous
#include <cuda_runtime.h>
#include <math.h>

// KarplusStrongResonator: (1 + q) Y = X, q = a1 z^-d1 + a2 z^-d2,
// d1 = 61 + argmax(delay_param + gumbel), d2 = 61 + ((argmax+1) % 360).
// Triple doubling: (1 - q^8) Y = (1-q)(1+q^2)(1+q^4) X. Three parallel FIR
// passes then a 9-tap recurrence, min lag 8*min(d1,d2) >= 488 (<=17 chunks).
// History buffers are zero-padded by PAD so NO lag guards are needed anywhere.

#define T_LEN 8192
#define B_ROWS 128
#define NDELAY 360
#define NT 512
#define NWARP (NT / 32)
#define PAD 3360   // >= 8 * max delay (8*419 = 3352), multiple of 4

__global__ __launch_bounds__(NT, 1)
void ks_resonator_kernel(const float* __restrict__ x,
                         const float* __restrict__ gumbel,
                         const float* __restrict__ dparam,
                         const float* __restrict__ fgain,
                         const float* __restrict__ refl,
                         float* __restrict__ out)
{
    extern __shared__ float smem[];
    float* A = smem + PAD;                  // A[-PAD .. T_LEN)
    float* B = smem + (2 * PAD + T_LEN);    // B[-PAD .. T_LEN)

    __shared__ float red_v[NWARP];
    __shared__ int   red_i[NWARP];
    __shared__ float s_a1, s_a2;
    __shared__ int   s_d1, s_d2;

    const int tid  = threadIdx.x;
    const int lane = tid & 31;
    const int wid  = tid >> 5;
    const int row  = blockIdx.x;

    // ---- async prefetch of x row into A[0..T) (non-blocking) ----
    {
        const char* gsrc = (const char*)(x + (size_t)row * T_LEN);
        #pragma unroll
        for (int i = tid; i < T_LEN / 4; i += NT) {
            unsigned sdst = (unsigned)__cvta_generic_to_shared(A + 4 * i);
            asm volatile("cp.async.cg.shared.global [%0], [%1], 16;\n"
                         :: "r"(sdst), "l"(gsrc + 16 * (size_t)i));
        }
        asm volatile("cp.async.commit_group;\n");
    }

    // ---- zero both pads (overlaps the cp.async fetch) ----
    {
        float4 z = make_float4(0.f, 0.f, 0.f, 0.f);
        float4* pa = reinterpret_cast<float4*>(smem);                       // A pad
        float4* pb = reinterpret_cast<float4*>(smem + PAD + T_LEN);        // B pad
        #pragma unroll
        for (int i = tid; i < PAD / 4; i += NT) { pa[i] = z; pb[i] = z; }
    }

    // ---- argmax(delay_param + gumbel) via shuffles (overlapped) ----
    {
        float v = -INFINITY;
        int   idx = 0;
        if (tid < NDELAY) { v = dparam[tid] + gumbel[tid]; idx = tid; }
        #pragma unroll
        for (int off = 16; off > 0; off >>= 1) {
            float v2 = __shfl_down_sync(0xffffffffu, v, off);
            int   i2 = __shfl_down_sync(0xffffffffu, idx, off);
            if (v2 > v || (v2 == v && i2 < idx)) { v = v2; idx = i2; }
        }
        if (lane == 0) { red_v[wid] = v; red_i[wid] = idx; }
        __syncthreads();
        if (wid == 0) {
            float vv = (lane < NWARP) ? red_v[lane] : -INFINITY;
            int   ii = (lane < NWARP) ? red_i[lane] : 0;
            #pragma unroll
            for (int off = 8; off > 0; off >>= 1) {
                float v2 = __shfl_down_sync(0xffffffffu, vv, off);
                int   i2 = __shfl_down_sync(0xffffffffu, ii, off);
                if (v2 > vv || (v2 == vv && i2 < ii)) { vv = v2; ii = i2; }
            }
            if (lane == 0) {
                int j = ii;
                float k1 = tanhf(tanhf(refl[0]));  // resonant_activation(tanh(rc), tau=0)
                float k2 = tanhf(tanhf(refl[1]));
                float a1 = k1 * (1.0f - k2);
                float a2 = fminf(fmaxf(k2, -0.999f), 0.999f);
                float a1b = 0.999f - fabsf(a2);
                a1 = fminf(fmaxf(a1, -a1b), a1b);
                float g = powf(1.0f / (1.0f + expf(-fgain[0])), 0.45f);
                s_a1 = a1 * g;
                s_a2 = a2 * g;
                s_d1 = 61 + j;
                s_d2 = 61 + ((j + 1) % NDELAY);
            }
        }
    }

    asm volatile("cp.async.wait_group 0;\n");
    __syncthreads();

    const float a1 = s_a1, a2 = s_a2;
    const int d1 = s_d1, d2 = s_d2;

    // q^2 taps
    const float c20 = a1 * a1, c21 = 2.0f * a1 * a2, c22 = a2 * a2;
    const int   l20 = 2 * d1,  l21 = d1 + d2,        l22 = 2 * d2;

    // q^4 taps
    const float c40 = c20 * c20;
    const float c41 = 4.0f * c20 * a1 * a2;
    const float c42 = 6.0f * c20 * c22;
    const float c43 = 4.0f * a1 * a2 * c22;
    const float c44 = c22 * c22;
    const int   l40 = 4 * d1, l41 = 3 * d1 + d2, l42 = 2 * (d1 + d2),
                l43 = d1 + 3 * d2, l44 = 4 * d2;

    // q^8 taps: C(8,i) a1^i a2^(8-i) at lag i*d1 + (8-i)*d2
    const float q8[9] = {
        c44 * c44,
        8.0f  * a1 * c22 * c22 * c22 * a2,
        28.0f * c20 * c22 * c22 * c22,
        56.0f * c20 * a1 * c22 * c22 * a2,
        70.0f * c40 * c44,
        56.0f * c40 * a1 * c22 * a2,
        28.0f * c40 * c20 * c22,
        8.0f  * c40 * c20 * a1 * a2,
        c40 * c40
    };
    int lg[9];
    #pragma unroll
    for (int i = 0; i < 9; i++) lg[i] = i * d1 + (8 - i) * d2;
    const int Cq = 8 * min(d1, d2);     // dependency-free chunk >= 488

    // ---- pass 0: B = (1 - q) A   (unguarded; pad supplies zeros) ----
    #pragma unroll 4
    for (int t = tid; t < T_LEN; t += NT)
        B[t] = fmaf(-a1, A[t - d1], fmaf(-a2, A[t - d2], A[t]));
    __syncthreads();

    // ---- pass 1: A = (1 + q^2) B ----
    #pragma unroll 4
    for (int t = tid; t < T_LEN; t += NT)
        A[t] = fmaf(c20, B[t - l20], fmaf(c21, B[t - l21], fmaf(c22, B[t - l22], B[t])));
    __syncthreads();

    // ---- pass 2: B = (1 + q^4) A ----
    #pragma unroll 4
    for (int t = tid; t < T_LEN; t += NT) {
        float acc0 = fmaf(c40, A[t - l40], fmaf(c41, A[t - l41], A[t]));
        float acc1 = fmaf(c42, A[t - l42], fmaf(c43, A[t - l43], c44 * A[t - l44]));
        B[t] = acc0 + acc1;
    }
    __syncthreads();

    // ---- recurrence: y[t] = B[t] + q^8 * y, in place on B; fused STG ----
    float* orow = out + (size_t)row * T_LEN;
    for (int base = 0; base < T_LEN; base += Cq) {
        const int end = min(base + Cq, T_LEN);
        for (int t = base + tid; t < end; t += NT) {
            float acc0 = fmaf(q8[0], B[t - lg[0]], B[t]);
            float acc1 = fmaf(q8[1], B[t - lg[1]], q8[2] * B[t - lg[2]]);
            float acc2 = fmaf(q8[3], B[t - lg[3]], q8[4] * B[t - lg[4]]);
            float acc3 = fmaf(q8[5], B[t - lg[5]], q8[6] * B[t - lg[6]]);
            float acc4 = fmaf(q8[7], B[t - lg[7]], q8[8] * B[t - lg[8]]);
            float acc  = (acc0 + acc1) + ((acc2 + acc3) + acc4);
            B[t] = acc;
            orow[t] = acc;   // fused, coalesced writeback
        }
        __syncthreads();
    }
}

extern "C" void kernel_launch(void* const* d_in, const int* in_sizes, int n_in,
                              void* d_out, int out_size)
{
    const float* excitation = (const float*)d_in[0];  // (128,1,8192)
    const float* gumbel     = (const float*)d_in[1];  // (360,)
    const float* dparam     = (const float*)d_in[2];  // (360,)
    const float* fgain      = (const float*)d_in[3];  // (1,)
    const float* refl       = (const float*)d_in[4];  // (2,)
    float* out = (float*)d_out;                       // (128,1,8192)

    const int smem_bytes = (2 * (T_LEN + PAD)) * sizeof(float); // ~92.4 KB
    cudaFuncSetAttribute(ks_resonator_kernel,
                         cudaFuncAttributeMaxDynamicSharedMemorySize, smem_bytes);

    ks_resonator_kernel<<<B_ROWS, NT, smem_bytes>>>(
        excitation, gumbel, dparam, fgain, refl, out);
}

// round 12
// speedup vs baseline: 1.2388x; 1.0239x over previous
#include <cuda_runtime.h>
#include <math.h>

// KarplusStrongResonator: (1 + q) Y = X, q = a1 z^-d1 + a2 z^-d2,
// d1 = 61 + argmax(delay_param + gumbel), d2 = 61 + ((argmax+1) % 360).
// Triple doubling: (1 - q^8) Y = (1-q)(1+q^2)(1+q^4) X.
// Fast path exploits d2 == d1+1: every q^k has a contiguous (k+1)-tap window,
// so 4-sample blocks read aligned float4 windows (16B/sample instead of 40B).
// Zero-padded history (PAD) removes all lag guards.

#define T_LEN 8192
#define B_ROWS 128
#define NDELAY 360
#define NT 512
#define NWARP (NT / 32)
#define PAD 3360   // == 8 * 420 (max lag), multiple of 4

__global__ __launch_bounds__(NT, 1)
void ks_resonator_kernel(const float* __restrict__ x,
                         const float* __restrict__ gumbel,
                         const float* __restrict__ dparam,
                         const float* __restrict__ fgain,
                         const float* __restrict__ refl,
                         float* __restrict__ out)
{
    extern __shared__ float smem[];
    float* A = smem + PAD;                  // A[-PAD .. T_LEN)
    float* B = smem + (2 * PAD + T_LEN);    // B[-PAD .. T_LEN)

    __shared__ float red_v[NWARP];
    __shared__ int   red_i[NWARP];
    __shared__ float s_a1, s_a2;
    __shared__ int   s_d1, s_d2;

    const int tid  = threadIdx.x;
    const int lane = tid & 31;
    const int wid  = tid >> 5;
    const int row  = blockIdx.x;

    // ---- async prefetch of x row into A[0..T) (non-blocking) ----
    {
        const char* gsrc = (const char*)(x + (size_t)row * T_LEN);
        #pragma unroll
        for (int i = tid; i < T_LEN / 4; i += NT) {
            unsigned sdst = (unsigned)__cvta_generic_to_shared(A + 4 * i);
            asm volatile("cp.async.cg.shared.global [%0], [%1], 16;\n"
                         :: "r"(sdst), "l"(gsrc + 16 * (size_t)i));
        }
        asm volatile("cp.async.commit_group;\n");
    }

    // ---- zero both pads (overlaps the cp.async fetch) ----
    {
        float4 z = make_float4(0.f, 0.f, 0.f, 0.f);
        float4* pa = reinterpret_cast<float4*>(smem);                 // A pad
        float4* pb = reinterpret_cast<float4*>(smem + PAD + T_LEN);   // B pad
        #pragma unroll
        for (int i = tid; i < PAD / 4; i += NT) { pa[i] = z; pb[i] = z; }
    }

    // ---- argmax(delay_param + gumbel) via shuffles (overlapped) ----
    {
        float v = -INFINITY;
        int   idx = 0;
        if (tid < NDELAY) { v = dparam[tid] + gumbel[tid]; idx = tid; }
        #pragma unroll
        for (int off = 16; off > 0; off >>= 1) {
            float v2 = __shfl_down_sync(0xffffffffu, v, off);
            int   i2 = __shfl_down_sync(0xffffffffu, idx, off);
            if (v2 > v || (v2 == v && i2 < idx)) { v = v2; idx = i2; }
        }
        if (lane == 0) { red_v[wid] = v; red_i[wid] = idx; }
        __syncthreads();
        if (wid == 0) {
            float vv = (lane < NWARP) ? red_v[lane] : -INFINITY;
            int   ii = (lane < NWARP) ? red_i[lane] : 0;
            #pragma unroll
            for (int off = 8; off > 0; off >>= 1) {
                float v2 = __shfl_down_sync(0xffffffffu, vv, off);
                int   i2 = __shfl_down_sync(0xffffffffu, ii, off);
                if (v2 > vv || (v2 == vv && i2 < ii)) { vv = v2; ii = i2; }
            }
            if (lane == 0) {
                int j = ii;
                float k1 = tanhf(tanhf(refl[0]));  // resonant_activation(tanh(rc), tau=0)
                float k2 = tanhf(tanhf(refl[1]));
                float a1 = k1 * (1.0f - k2);
                float a2 = fminf(fmaxf(k2, -0.999f), 0.999f);
                float a1b = 0.999f - fabsf(a2);
                a1 = fminf(fmaxf(a1, -a1b), a1b);
                float g = powf(1.0f / (1.0f + expf(-fgain[0])), 0.45f);
                s_a1 = a1 * g;
                s_a2 = a2 * g;
                s_d1 = 61 + j;
                s_d2 = 61 + ((j + 1) % NDELAY);
            }
        }
    }

    asm volatile("cp.async.wait_group 0;\n");
    __syncthreads();

    const float a1 = s_a1, a2 = s_a2;
    const int d1 = s_d1, d2 = s_d2;

    // Binomial tap arrays: qNc[k] = C(N,k) a1^k a2^(N-k)
    float q2c[3], q4c[5], q8c[9];
    {
        float p1[9], p2[9];
        p1[0] = 1.f; p2[0] = 1.f;
        #pragma unroll
        for (int i = 1; i < 9; i++) { p1[i] = p1[i-1] * a1; p2[i] = p2[i-1] * a2; }
        const float C8[9] = {1.f, 8.f, 28.f, 56.f, 70.f, 56.f, 28.f, 8.f, 1.f};
        const float C4[5] = {1.f, 4.f, 6.f, 4.f, 1.f};
        #pragma unroll
        for (int k = 0; k < 9; k++) q8c[k] = C8[k] * p1[k] * p2[8 - k];
        #pragma unroll
        for (int k = 0; k < 5; k++) q4c[k] = C4[k] * p1[k] * p2[4 - k];
        q2c[0] = p2[2]; q2c[1] = 2.f * a1 * a2; q2c[2] = p1[2];
    }

    float* orow = out + (size_t)row * T_LEN;

    if (d2 == d1 + 1) {
        // ================= FAST PATH: contiguous tap windows =================
        // pass A: B = (1 - q) A   (2-tap window, scalar)
        #pragma unroll 4
        for (int t = tid; t < T_LEN; t += NT)
            B[t] = fmaf(-a1, A[t - d1], fmaf(-a2, A[t - d1 - 1], A[t]));
        __syncthreads();

        // pass B: A = (1 + q^2) B  (3-tap window at lag 2d1+2, scalar)
        {
            const int L = 2 * d1 + 2;
            #pragma unroll 4
            for (int t = tid; t < T_LEN; t += NT)
                A[t] = fmaf(q2c[0], B[t - L],
                       fmaf(q2c[1], B[t - L + 1],
                       fmaf(q2c[2], B[t - L + 2], B[t])));
        }
        __syncthreads();

        // pass C: B = (1 + q^4) A  (5-tap window; 4-sample float4 blocks)
        // window base t0 - (4d1+4) is 0 mod 4 -> aligned LDS.128
        {
            const int L = 4 * d1 + 4;
            #pragma unroll 4
            for (int t0 = 4 * tid; t0 < T_LEN; t0 += 4 * NT) {
                float4 cv = *reinterpret_cast<const float4*>(&A[t0]);
                float4 w0 = *reinterpret_cast<const float4*>(&A[t0 - L]);
                float4 w1 = *reinterpret_cast<const float4*>(&A[t0 - L + 4]);
                float W[8] = {w0.x, w0.y, w0.z, w0.w, w1.x, w1.y, w1.z, w1.w};
                float Cn[4] = {cv.x, cv.y, cv.z, cv.w};
                float acc[4];
                #pragma unroll
                for (int s = 0; s < 4; s++) {
                    float a = Cn[s];
                    #pragma unroll
                    for (int k = 0; k < 5; k++) a = fmaf(q4c[k], W[s + k], a);
                    acc[s] = a;
                }
                *reinterpret_cast<float4*>(&B[t0]) =
                    make_float4(acc[0], acc[1], acc[2], acc[3]);
            }
        }
        __syncthreads();

        // recurrence: y = B + q^8 y in place (9-tap window at lag 8d1+8);
        // chunk = 8d1 (multiple of 4), window reads land strictly before chunk.
        {
            const int L  = 8 * d1 + 8;
            const int Cq = 8 * d1;
            for (int base = 0; base < T_LEN; base += Cq) {
                const int end = min(base + Cq, T_LEN);
                for (int t0 = base + 4 * tid; t0 < end; t0 += 4 * NT) {
                    float4 cv = *reinterpret_cast<const float4*>(&B[t0]);
                    float4 w0 = *reinterpret_cast<const float4*>(&B[t0 - L]);
                    float4 w1 = *reinterpret_cast<const float4*>(&B[t0 - L + 4]);
                    float4 w2 = *reinterpret_cast<const float4*>(&B[t0 - L + 8]);
                    float W[12] = {w0.x, w0.y, w0.z, w0.w,
                                   w1.x, w1.y, w1.z, w1.w,
                                   w2.x, w2.y, w2.z, w2.w};
                    float Cn[4] = {cv.x, cv.y, cv.z, cv.w};
                    float acc[4];
                    #pragma unroll
                    for (int s = 0; s < 4; s++) {
                        float a = Cn[s];
                        #pragma unroll
                        for (int k = 0; k < 9; k++) a = fmaf(q8c[k], W[s + k], a);
                        acc[s] = a;
                    }
                    float4 r = make_float4(acc[0], acc[1], acc[2], acc[3]);
                    *reinterpret_cast<float4*>(&B[t0]) = r;
                    *reinterpret_cast<float4*>(&orow[t0]) = r;   // fused writeback
                }
                __syncthreads();
            }
        }
    } else {
        // ================= GENERIC PATH (j == 359): scalar =================
        const int l20 = 2 * d1, l21 = d1 + d2, l22 = 2 * d2;
        int l4[5], lg[9];
        #pragma unroll
        for (int i = 0; i < 5; i++) l4[i] = i * d1 + (4 - i) * d2;
        #pragma unroll
        for (int i = 0; i < 9; i++) lg[i] = i * d1 + (8 - i) * d2;
        const int Cq = 8 * min(d1, d2);

        #pragma unroll 4
        for (int t = tid; t < T_LEN; t += NT)
            B[t] = fmaf(-a1, A[t - d1], fmaf(-a2, A[t - d2], A[t]));
        __syncthreads();

        #pragma unroll 4
        for (int t = tid; t < T_LEN; t += NT)
            A[t] = fmaf(q2c[2], B[t - l20],
                   fmaf(q2c[1], B[t - l21],
                   fmaf(q2c[0], B[t - l22], B[t])));
        __syncthreads();

        #pragma unroll 4
        for (int t = tid; t < T_LEN; t += NT) {
            float acc = A[t];
            #pragma unroll
            for (int i = 0; i < 5; i++) acc = fmaf(q4c[i], A[t - l4[i]], acc);
            B[t] = acc;
        }
        __syncthreads();

        for (int base = 0; base < T_LEN; base += Cq) {
            const int end = min(base + Cq, T_LEN);
            for (int t = base + tid; t < end; t += NT) {
                float acc = B[t];
                #pragma unroll
                for (int i = 0; i < 9; i++) acc = fmaf(q8c[i], B[t - lg[i]], acc);
                B[t] = acc;
                orow[t] = acc;
            }
            __syncthreads();
        }
    }
}

extern "C" void kernel_launch(void* const* d_in, const int* in_sizes, int n_in,
                              void* d_out, int out_size)
{
    const float* excitation = (const float*)d_in[0];  // (128,1,8192)
    const float* gumbel     = (const float*)d_in[1];  // (360,)
    const float* dparam     = (const float*)d_in[2];  // (360,)
    const float* fgain      = (const float*)d_in[3];  // (1,)
    const float* refl       = (const float*)d_in[4];  // (2,)
    float* out = (float*)d_out;                       // (128,1,8192)

    const int smem_bytes = (2 * (T_LEN + PAD)) * sizeof(float); // ~92.4 KB
    cudaFuncSetAttribute(ks_resonator_kernel,
                         cudaFuncAttributeMaxDynamicSharedMemorySize, smem_bytes);

    ks_resonator_kernel<<<B_ROWS, NT, smem_bytes>>>(
        excitation, gumbel, dparam, fgain, refl, out);
}